// round 7
// baseline (speedup 1.0000x reference)
#include <cuda_runtime.h>
#include <math.h>
#include <stdint.h>

// Problem constants: B=2, T=2048, C=1024, H=16, hd=64
constexpr int kT  = 2048;
constexpr int kC  = 1024;
constexpr int kH  = 16;
constexpr int kHD = 64;
constexpr int kB  = 2;

// Scratch (allocation-free rule: __device__ globals)
__device__ float g_q[kB * kH * kT * kHD];     // Q in [B,H,T,hd]   (16 MB)
__device__ float g_yatt[kB * kT * kC];        // attention out, [B,T,C] (16 MB)

// ---------------------------------------------------------------------------
// TF32 helpers
// ---------------------------------------------------------------------------
__device__ __forceinline__ float to_tf32(float x) {
    float r;
    asm("cvt.rna.tf32.f32 %0, %1;" : "=f"(r) : "f"(x));
    return r;
}

__device__ __forceinline__ void mma_tf32(float* c, const uint32_t* a, const uint32_t* b) {
    asm volatile(
        "mma.sync.aligned.m16n8k8.row.col.f32.tf32.tf32.f32 "
        "{%0,%1,%2,%3}, {%4,%5,%6,%7}, {%8,%9}, {%0,%1,%2,%3};\n"
        : "+f"(c[0]), "+f"(c[1]), "+f"(c[2]), "+f"(c[3])
        : "r"(a[0]), "r"(a[1]), "r"(a[2]), "r"(a[3]), "r"(b[0]), "r"(b[1]));
}

// ---------------------------------------------------------------------------
// TF32 MMA GEMM v2. CTA 128x128, BK=32, 128 threads (4 warps: 2m x 2n),
// warp tile 64x64. Double-buffered fragment-order smem + pipelined LDG.
//
// Smem (per buffer 16KB + 16KB):
//   AsF[kc(4)][mt(8)][j(4)][slot(32)]   slot = lane ^ ((kc*2 + (j>>1))*4)
//   BsF[kc(4)][nt(16)][j(2)][slot(32)]  slot = lane ^ ((nt&7)*4)
// Fragment semantics (m16n8k8, lane: gid=lane>>2, tig=lane&3):
//   A j=0:(gid,tig) j=1:(gid+8,tig) j=2:(gid,tig+4) j=3:(gid+8,tig+4)
//   B j=0:(tig,gid) j=1:(tig+4,gid)
// ---------------------------------------------------------------------------
constexpr int kGemmSmemBytes = 2 * (16384 + 16384);   // 64 KB

template <int N_, typename Epilogue>
__device__ __forceinline__ void gemm_tf32_core(
    const float* __restrict__ A, const float* __restrict__ W,
    Epilogue epi)
{
    constexpr int K = kC;  // 1024
    extern __shared__ float smf[];
    float* AsF = smf;               // [2][4096]
    float* BsF = smf + 2 * 4096;    // [2][4096]

    const int m0 = blockIdx.y * 128;
    const int n0 = blockIdx.x * 128;
    const int tid  = threadIdx.x;
    const int lane = tid & 31;
    const int wid  = tid >> 5;
    const int wm = wid >> 1;      // 0..1
    const int wn = wid & 1;       // 0..1

    float acc[4][8][4];
#pragma unroll
    for (int i = 0; i < 4; i++)
#pragma unroll
        for (int j = 0; j < 8; j++)
#pragma unroll
            for (int c = 0; c < 4; c++) acc[i][j][c] = 0.f;

    float4 aR[8], bR[8];

    // ---- staging address precompute (per-thread constants) ----
    // A: f = it*128 + tid
    int a_r[8], a_dst[8], a_xor[8];
    int b_dst[8], b_xor[8], b_kk[8], b_c4[8];
#pragma unroll
    for (int it = 0; it < 8; it++) {
        int f = it * 128 + tid;
        int r = f >> 3, kq = f & 7;
        int kc = kq >> 1, jc = kq & 1;
        int mt = r >> 4, rr = r & 15;
        int jr = rr >> 3;
        a_r[it]   = r;
        a_xor[it] = kq * 4;
        a_dst[it] = (((kc * 8 + mt) * 4) + (jr + 2 * jc)) * 32 + ((rr & 7) * 4);
        int kk = f >> 5, c4 = f & 31;
        int kc2 = kk >> 3, k7 = kk & 7;
        int tig2 = k7 & 3, jb = k7 >> 2;
        int nt = c4 >> 1;
        b_kk[it] = kk; b_c4[it] = c4;
        b_xor[it] = (nt & 7) * 4;
        b_dst[it] = (((kc2 * 16 + nt) * 2) + jb) * 32 + ((c4 & 1) * 16) + tig2;
    }

    auto load_slab = [&](int k0) {
#pragma unroll
        for (int it = 0; it < 8; it++)
            aR[it] = *reinterpret_cast<const float4*>(A + (size_t)(m0 + a_r[it]) * K + k0 + (a_xor[it]));
        // note: a_xor[it] == kq*4 == k-offset of the float4 within the slab
#pragma unroll
        for (int it = 0; it < 8; it++)
            bR[it] = *reinterpret_cast<const float4*>(W + (size_t)(k0 + b_kk[it]) * N_ + n0 + b_c4[it] * 4);
    };

    auto store_slab = [&](int buf) {
        float* ab = AsF + buf * 4096;
        float* bb = BsF + buf * 4096;
#pragma unroll
        for (int it = 0; it < 8; it++) {
            float* d = ab + (a_dst[it] & ~127) ;
            int basep = a_dst[it] & 127;        // (frag block offset*32 folded) — recompute:
            (void)basep;
            // direct: element index = a_dst[it] - (rr&7)*4 + ((gid*4 + i) ^ xor)
        }
        // (real stores below)
#pragma unroll
        for (int it = 0; it < 8; it++) {
            int blockbase = a_dst[it] - (a_dst[it] & 127) ; // not used
            (void)blockbase;
        }
#pragma unroll
        for (int it = 0; it < 8; it++) {
            int base = (a_dst[it] / 32) * 32;   // fragment-row base
            int g4   = a_dst[it] - base;        // (rr&7)*4
            float* d = ab + base;
            int xo = a_xor[it];
            d[(g4 + 0) ^ xo] = to_tf32(aR[it].x);
            d[(g4 + 1) ^ xo] = to_tf32(aR[it].y);
            d[(g4 + 2) ^ xo] = to_tf32(aR[it].z);
            d[(g4 + 3) ^ xo] = to_tf32(aR[it].w);
        }
#pragma unroll
        for (int it = 0; it < 8; it++) {
            int base = (b_dst[it] / 32) * 32;
            int rem  = b_dst[it] - base;        // g0*4 + tig
            float* d = bb + base;
            int xo = b_xor[it];
            d[(rem + 0) ^ xo]  = to_tf32(bR[it].x);
            d[(rem + 4) ^ xo]  = to_tf32(bR[it].y);
            d[(rem + 8) ^ xo]  = to_tf32(bR[it].z);
            d[(rem + 12) ^ xo] = to_tf32(bR[it].w);
        }
    };

    auto compute = [&](int buf) {
        const float* ab = AsF + buf * 4096;
        const float* bb = BsF + buf * 4096;
#pragma unroll
        for (int kc = 0; kc < 4; kc++) {
            uint32_t a[4][4], b[8][2];
#pragma unroll
            for (int mt = 0; mt < 4; mt++) {
                const float* ap = ab + ((kc * 8 + wm * 4 + mt) * 4) * 32;
#pragma unroll
                for (int j = 0; j < 4; j++) {
                    int xo = (kc * 2 + (j >> 1)) * 4;
                    a[mt][j] = __float_as_uint(ap[j * 32 + (lane ^ xo)]);
                }
            }
#pragma unroll
            for (int nt = 0; nt < 8; nt++) {
                int ntg = wn * 8 + nt;
                const float* bp = bb + ((kc * 16 + ntg) * 2) * 32;
                int xo = (ntg & 7) * 4;
                b[nt][0] = __float_as_uint(bp[(lane ^ xo)]);
                b[nt][1] = __float_as_uint(bp[32 + (lane ^ xo)]);
            }
#pragma unroll
            for (int mt = 0; mt < 4; mt++)
#pragma unroll
                for (int nt = 0; nt < 8; nt++)
                    mma_tf32(acc[mt][nt], a[mt], b[nt]);
        }
    };

    // ---- pipelined mainloop ----
    load_slab(0);
    store_slab(0);
    __syncthreads();
    for (int s = 0; s < K / 32; s++) {
        if (s + 1 < K / 32) load_slab((s + 1) * 32);
        compute(s & 1);
        if (s + 1 < K / 32) {
            store_slab((s + 1) & 1);
        }
        __syncthreads();
    }

    // ---- epilogue ----
    const int gid = lane >> 2, tig = lane & 3;
#pragma unroll
    for (int mt = 0; mt < 4; mt++)
#pragma unroll
        for (int nt = 0; nt < 8; nt++)
#pragma unroll
            for (int c = 0; c < 4; c++) {
                int m = m0 + wm * 64 + mt * 16 + gid + 8 * (c >> 1);
                int n = n0 + wn * 64 + nt * 8 + tig * 2 + (c & 1);
                epi(m, n, acc[mt][nt][c]);
            }
}

struct QkvEpilogue {
    const float* bias;
    float* kout;
    float* vout;
    __device__ __forceinline__ void operator()(int m, int n, float v) const {
        v += bias[n];
        int bidx = m >> 11;
        int t    = m & 2047;
        int s = n >> 10;
        int cc = n & 1023;
        int h = cc >> 6, d = cc & 63;
        int idx = ((bidx * kH + h) * kT + t) * kHD + d;
        if (s == 0)      g_q[idx]  = v;
        else if (s == 1) kout[idx] = v;
        else             vout[idx] = v;
    }
};

__global__ void __launch_bounds__(128) qkv_gemm_kernel(
    const float* __restrict__ A, const float* __restrict__ W,
    const float* __restrict__ bias,
    float* __restrict__ kout, float* __restrict__ vout)
{
    QkvEpilogue epi{bias, kout, vout};
    gemm_tf32_core<3 * kC>(A, W, epi);
}

struct ProjEpilogue {
    const float* bias;
    float* out;
    __device__ __forceinline__ void operator()(int m, int n, float v) const {
        out[(size_t)m * kC + n] = v + bias[n];
    }
};

__global__ void __launch_bounds__(128) proj_gemm_kernel(
    const float* __restrict__ W, const float* __restrict__ bias,
    float* __restrict__ out)
{
    ProjEpilogue epi{bias, out};
    gemm_tf32_core<kC>(g_yatt, W, epi);
}

// ---------------------------------------------------------------------------
// TF32 MMA flash attention (unchanged from R3). BR=BC=64, 128 threads.
// ---------------------------------------------------------------------------
constexpr int kFlashSmemBytes = 3 * 64 * 68 * 4;

__global__ void __launch_bounds__(128) flash_kernel(
    const float* __restrict__ Kg, const float* __restrict__ Vg)
{
    extern __shared__ float sm[];
    float* Ks = sm;               // [64][68]
    float* Vt = sm + 64 * 68;     // [64][68]  (Vt[d][c])
    float* Ss = sm + 2 * 64 * 68; // [64][68]

    const int tid  = threadIdx.x;
    const int lane = tid & 31;
    const int wid  = tid >> 5;
    const int gid  = lane >> 2;
    const int tig  = lane & 3;
    const int qi = blockIdx.x, h = blockIdx.y, b = blockIdx.z;
    const int qbase = qi * 64;
    const int r0 = wid * 16;

    const size_t head_off = (size_t)(b * kH + h) * kT * kHD;
    const float* Qp = g_q + head_off;
    const float* Kp = Kg + head_off;
    const float* Vp = Vg + head_off;

#pragma unroll
    for (int it = 0; it < 8; it++) {
        int f = it * 128 + tid;
        int r = f >> 4, dq = (f & 15) * 4;
        float4 q4 = *reinterpret_cast<const float4*>(Qp + (size_t)(qbase + r) * kHD + dq);
        float* d = Ss + r * 68 + dq;
        d[0] = q4.x; d[1] = q4.y; d[2] = q4.z; d[3] = q4.w;
    }
    __syncthreads();

    uint32_t qf[8][4];
#pragma unroll
    for (int kc = 0; kc < 8; kc++) {
        const float* base = Ss + (r0 + gid) * 68 + kc * 8 + tig;
        qf[kc][0] = __float_as_uint(to_tf32(0.125f * base[0]));
        qf[kc][1] = __float_as_uint(to_tf32(0.125f * base[8 * 68]));
        qf[kc][2] = __float_as_uint(to_tf32(0.125f * base[4]));
        qf[kc][3] = __float_as_uint(to_tf32(0.125f * base[8 * 68 + 4]));
    }

    float mA = -INFINITY, mB = -INFINITY, lA = 0.f, lB = 0.f;
    float oacc[8][4];
#pragma unroll
    for (int nt = 0; nt < 8; nt++)
#pragma unroll
        for (int c = 0; c < 4; c++) oacc[nt][c] = 0.f;

    const int ntiles = qi + 1;
    const int vdpb = tid & 15, vcb4 = tid >> 4;

    for (int jt = 0; jt < ntiles; jt++) {
        __syncthreads();
#pragma unroll
        for (int it = 0; it < 8; it++) {
            int f = it * 128 + tid;
            int r = f >> 4, dq = (f & 15) * 4;
            float4 k4 = *reinterpret_cast<const float4*>(Kp + (size_t)(jt * 64 + r) * kHD + dq);
            float* d = Ks + r * 68 + dq;
            d[0] = to_tf32(k4.x); d[1] = to_tf32(k4.y);
            d[2] = to_tf32(k4.z); d[3] = to_tf32(k4.w);
        }
#pragma unroll
        for (int it = 0; it < 2; it++) {
            int cb = vcb4 + 8 * it;
            const float* vsrc = Vp + (size_t)(jt * 64 + cb * 4) * kHD + vdpb * 4;
            float4 a0 = *reinterpret_cast<const float4*>(vsrc);
            float4 a1 = *reinterpret_cast<const float4*>(vsrc + kHD);
            float4 a2 = *reinterpret_cast<const float4*>(vsrc + 2 * kHD);
            float4 a3 = *reinterpret_cast<const float4*>(vsrc + 3 * kHD);
            float4 t0 = {to_tf32(a0.x), to_tf32(a1.x), to_tf32(a2.x), to_tf32(a3.x)};
            float4 t1 = {to_tf32(a0.y), to_tf32(a1.y), to_tf32(a2.y), to_tf32(a3.y)};
            float4 t2 = {to_tf32(a0.z), to_tf32(a1.z), to_tf32(a2.z), to_tf32(a3.z)};
            float4 t3 = {to_tf32(a0.w), to_tf32(a1.w), to_tf32(a2.w), to_tf32(a3.w)};
            *reinterpret_cast<float4*>(Vt + (vdpb * 4 + 0) * 68 + cb * 4) = t0;
            *reinterpret_cast<float4*>(Vt + (vdpb * 4 + 1) * 68 + cb * 4) = t1;
            *reinterpret_cast<float4*>(Vt + (vdpb * 4 + 2) * 68 + cb * 4) = t2;
            *reinterpret_cast<float4*>(Vt + (vdpb * 4 + 3) * 68 + cb * 4) = t3;
        }
        __syncthreads();

        float sa[8][4];
#pragma unroll
        for (int nt = 0; nt < 8; nt++)
#pragma unroll
            for (int c = 0; c < 4; c++) sa[nt][c] = 0.f;
#pragma unroll
        for (int kc = 0; kc < 8; kc++) {
#pragma unroll
            for (int nt = 0; nt < 8; nt++) {
                const float* bp = Ks + (nt * 8 + gid) * 68 + kc * 8 + tig;
                uint32_t bb[2];
                bb[0] = __float_as_uint(bp[0]);
                bb[1] = __float_as_uint(bp[4]);
                mma_tf32(sa[nt], qf[kc], bb);
            }
        }

        if (jt == qi) {
            int rowA = r0 + gid, rowB = rowA + 8;
#pragma unroll
            for (int nt = 0; nt < 8; nt++) {
                int c0 = nt * 8 + tig * 2, c1 = c0 + 1;
                if (c0 > rowA) sa[nt][0] = -INFINITY;
                if (c1 > rowA) sa[nt][1] = -INFINITY;
                if (c0 > rowB) sa[nt][2] = -INFINITY;
                if (c1 > rowB) sa[nt][3] = -INFINITY;
            }
        }

        float mxA = -INFINITY, mxB = -INFINITY;
#pragma unroll
        for (int nt = 0; nt < 8; nt++) {
            mxA = fmaxf(mxA, fmaxf(sa[nt][0], sa[nt][1]));
            mxB = fmaxf(mxB, fmaxf(sa[nt][2], sa[nt][3]));
        }
        mxA = fmaxf(mxA, __shfl_xor_sync(0xffffffff, mxA, 1));
        mxA = fmaxf(mxA, __shfl_xor_sync(0xffffffff, mxA, 2));
        mxB = fmaxf(mxB, __shfl_xor_sync(0xffffffff, mxB, 1));
        mxB = fmaxf(mxB, __shfl_xor_sync(0xffffffff, mxB, 2));

        float mnA = fmaxf(mA, mxA), mnB = fmaxf(mB, mxB);
        float alphaA = __expf(mA - mnA), alphaB = __expf(mB - mnB);

        float sumA = 0.f, sumB = 0.f;
        float* prowA = Ss + (r0 + gid) * 68 + tig * 2;
        float* prowB = prowA + 8 * 68;
#pragma unroll
        for (int nt = 0; nt < 8; nt++) {
            float p0 = __expf(sa[nt][0] - mnA);
            float p1 = __expf(sa[nt][1] - mnA);
            float p2 = __expf(sa[nt][2] - mnB);
            float p3 = __expf(sa[nt][3] - mnB);
            float q0 = to_tf32(p0), q1 = to_tf32(p1);
            float q2 = to_tf32(p2), q3 = to_tf32(p3);
            sumA += q0 + q1;
            sumB += q2 + q3;
            prowA[nt * 8 + 0] = q0; prowA[nt * 8 + 1] = q1;
            prowB[nt * 8 + 0] = q2; prowB[nt * 8 + 1] = q3;
        }
        sumA += __shfl_xor_sync(0xffffffff, sumA, 1);
        sumA += __shfl_xor_sync(0xffffffff, sumA, 2);
        sumB += __shfl_xor_sync(0xffffffff, sumB, 1);
        sumB += __shfl_xor_sync(0xffffffff, sumB, 2);

        lA = lA * alphaA + sumA;  mA = mnA;
        lB = lB * alphaB + sumB;  mB = mnB;

#pragma unroll
        for (int nt = 0; nt < 8; nt++) {
            oacc[nt][0] *= alphaA; oacc[nt][1] *= alphaA;
            oacc[nt][2] *= alphaB; oacc[nt][3] *= alphaB;
        }
        __syncwarp();

#pragma unroll
        for (int kc = 0; kc < 8; kc++) {
            const float* ap = Ss + (r0 + gid) * 68 + kc * 8 + tig;
            uint32_t pa[4];
            pa[0] = __float_as_uint(ap[0]);
            pa[1] = __float_as_uint(ap[8 * 68]);
            pa[2] = __float_as_uint(ap[4]);
            pa[3] = __float_as_uint(ap[8 * 68 + 4]);
#pragma unroll
            for (int nt = 0; nt < 8; nt++) {
                const float* bp = Vt + (nt * 8 + gid) * 68 + kc * 8 + tig;
                uint32_t bb[2];
                bb[0] = __float_as_uint(bp[0]);
                bb[1] = __float_as_uint(bp[4]);
                mma_tf32(oacc[nt], pa, bb);
            }
        }
        __syncwarp();
    }

    float ilA = 1.f / lA, ilB = 1.f / lB;
    float* ypA = g_yatt + ((size_t)(b * kT + qbase + r0 + gid)) * kC + h * kHD;
    float* ypB = ypA + (size_t)8 * kC;
#pragma unroll
    for (int nt = 0; nt < 8; nt++) {
        float2 vA = {oacc[nt][0] * ilA, oacc[nt][1] * ilA};
        float2 vB = {oacc[nt][2] * ilB, oacc[nt][3] * ilB};
        *reinterpret_cast<float2*>(ypA + nt * 8 + tig * 2) = vA;
        *reinterpret_cast<float2*>(ypB + nt * 8 + tig * 2) = vB;
    }
}

// ---------------------------------------------------------------------------
// Launch: qkv -> flash -> proj, sequential on default stream (capturable).
// Output layout: [ y (B*T*C) | k (B*H*T*hd) | v (B*H*T*hd) ]
// ---------------------------------------------------------------------------
extern "C" void kernel_launch(void* const* d_in, const int* in_sizes, int n_in,
                              void* d_out, int out_size)
{
    const float* x      = (const float*)d_in[0];
    const float* W_attn = (const float*)d_in[1];
    const float* b_attn = (const float*)d_in[2];
    const float* W_proj = (const float*)d_in[3];
    const float* b_proj = (const float*)d_in[4];

    float* y = (float*)d_out;
    const int seg = out_size / 3;       // 4,194,304 each
    float* kout = y + seg;
    float* vout = y + 2 * seg;

    cudaFuncSetAttribute(qkv_gemm_kernel,
                         cudaFuncAttributeMaxDynamicSharedMemorySize, kGemmSmemBytes);
    cudaFuncSetAttribute(proj_gemm_kernel,
                         cudaFuncAttributeMaxDynamicSharedMemorySize, kGemmSmemBytes);
    cudaFuncSetAttribute(flash_kernel,
                         cudaFuncAttributeMaxDynamicSharedMemorySize, kFlashSmemBytes);

    // QKV: M=4096 -> 32 m-tiles, N=3072 -> 24 n-tiles
    qkv_gemm_kernel<<<dim3(24, 32), 128, kGemmSmemBytes>>>(x, W_attn, b_attn, kout, vout);
    // Attention: (T/64, H, B)
    flash_kernel<<<dim3(32, 16, 2), 128, kFlashSmemBytes>>>(kout, vout);
    // Proj: N=1024 -> 8 n-tiles
    proj_gemm_kernel<<<dim3(8, 32), 128, kGemmSmemBytes>>>(W_proj, b_proj, y);
}

// round 10
// speedup vs baseline: 1.2423x; 1.2423x over previous
#include <cuda_runtime.h>
#include <math.h>
#include <stdint.h>

// Problem constants: B=2, T=2048, C=1024, H=16, hd=64
constexpr int kT  = 2048;
constexpr int kC  = 1024;
constexpr int kH  = 16;
constexpr int kHD = 64;
constexpr int kB  = 2;

// Scratch (allocation-free rule: __device__ globals)
__device__ float g_q[kB * kH * kT * kHD];     // Q in [B,H,T,hd]        (16 MB)
__device__ float g_yatt[kB * kT * kC];        // attn out (tf32-rounded) (16 MB)
__device__ float g_xc[kB * kT * kC];          // x, tf32-rounded         (16 MB)
__device__ float g_wc[kC * 3 * kC];           // W_attn, tf32-rounded    (12 MB)
__device__ float g_wp[kC * kC];               // W_proj, tf32-rounded    ( 4 MB)

// ---------------------------------------------------------------------------
// TF32 + cp.async helpers
// ---------------------------------------------------------------------------
__device__ __forceinline__ float to_tf32(float x) {
    float r;
    asm("cvt.rna.tf32.f32 %0, %1;" : "=f"(r) : "f"(x));
    return r;
}

__device__ __forceinline__ void mma_tf32(float* c, const uint32_t* a, const uint32_t* b) {
    asm volatile(
        "mma.sync.aligned.m16n8k8.row.col.f32.tf32.tf32.f32 "
        "{%0,%1,%2,%3}, {%4,%5,%6,%7}, {%8,%9}, {%0,%1,%2,%3};\n"
        : "+f"(c[0]), "+f"(c[1]), "+f"(c[2]), "+f"(c[3])
        : "r"(a[0]), "r"(a[1]), "r"(a[2]), "r"(a[3]), "r"(b[0]), "r"(b[1]));
}

__device__ __forceinline__ uint32_t smem_u32(const void* p) {
    uint32_t a;
    asm("{ .reg .u64 t; cvta.to.shared.u64 t, %1; cvt.u32.u64 %0, t; }"
        : "=r"(a) : "l"(p));
    return a;
}

#define CP_ASYNC16(saddr, gptr) \
    asm volatile("cp.async.cg.shared.global [%0], [%1], 16;" \
                 :: "r"(saddr), "l"(gptr) : "memory")
#define CP_COMMIT() asm volatile("cp.async.commit_group;" ::: "memory")
#define CP_WAIT1()  asm volatile("cp.async.wait_group 1;" ::: "memory")
#define CP_WAIT0()  asm volatile("cp.async.wait_group 0;" ::: "memory")

// ---------------------------------------------------------------------------
// Pre-round inputs to tf32 (single RNA rounding; hot loops stay cvt-free).
// One launch covers x -> g_xc, W_attn -> g_wc, W_proj -> g_wp (float4 ranges).
// ---------------------------------------------------------------------------
constexpr int kX4  = kB * kT * kC / 4;        // 1048576
constexpr int kWA4 = kC * 3 * kC / 4;         //  786432
constexpr int kWP4 = kC * kC / 4;             //  262144
constexpr int kCvtTotal4 = kX4 + kWA4 + kWP4; // 2097152

__global__ void __launch_bounds__(256) cvt_tf32_kernel(
    const float* __restrict__ x, const float* __restrict__ wa,
    const float* __restrict__ wp)
{
    int i = blockIdx.x * blockDim.x + threadIdx.x;
    const float4* src;
    float4* dst;
    if (i < kX4) {
        src = reinterpret_cast<const float4*>(x) + i;
        dst = reinterpret_cast<float4*>(g_xc) + i;
    } else if (i < kX4 + kWA4) {
        src = reinterpret_cast<const float4*>(wa) + (i - kX4);
        dst = reinterpret_cast<float4*>(g_wc) + (i - kX4);
    } else {
        src = reinterpret_cast<const float4*>(wp) + (i - kX4 - kWA4);
        dst = reinterpret_cast<float4*>(g_wp) + (i - kX4 - kWA4);
    }
    float4 v = *src;
    float4 o = {to_tf32(v.x), to_tf32(v.y), to_tf32(v.z), to_tf32(v.w)};
    *dst = o;
}

// ---------------------------------------------------------------------------
// TF32 MMA GEMM v3. CTA 128x128, BK=32, 256 threads (8 warps: 2m x 4n),
// warp tile 64x32. cp.async double-buffered staging into LINEAR padded smem:
//   As[2][128][36]  (stride 36: frag bank = 4*gid+tig = lane, conflict-free)
//   Bs[2][32][136]  (stride 136: frag bank = 8*tig+gid, bijective, CF)
// Inputs must already be tf32-rounded (g_xc/g_wc/g_wp/g_yatt).
// ---------------------------------------------------------------------------
constexpr int kAStrideF = 36;   // floats; 144 B/row
constexpr int kBStrideF = 136;  // floats; 544 B/row
constexpr int kABufF = 128 * kAStrideF;   // 4608 floats = 18432 B
constexpr int kBBufF = 32 * kBStrideF;    // 4352 floats = 17408 B
constexpr int kGemmSmemBytes = (2 * kABufF + 2 * kBBufF) * 4;  // 71680

template <int N_, typename Epilogue>
__device__ __forceinline__ void gemm_tf32_core(
    const float* __restrict__ A, const float* __restrict__ W,
    Epilogue epi)
{
    constexpr int K = kC;  // 1024
    extern __shared__ float smf[];
    float* As = smf;                    // [2][4608]
    float* Bs = smf + 2 * kABufF;       // [2][4352]

    const int m0 = blockIdx.y * 128;
    const int n0 = blockIdx.x * 128;
    const int tid  = threadIdx.x;
    const int lane = tid & 31;
    const int wid  = tid >> 5;
    const int wm = wid >> 2;      // 0..1
    const int wn = wid & 3;       // 0..3
    const int gid = lane >> 2, tig = lane & 3;

    const uint32_t aBase = smem_u32(As);
    const uint32_t bBase = smem_u32(Bs);

    // ---- per-thread staging constants ----
    // A: 4 chunks of 16B: row = it*32 + (tid>>3), k-chunk = (tid&7)
    const int aRow = tid >> 3;            // + it*32
    const int aC16 = tid & 7;
    const float* aG[4];
    uint32_t aS[4];
#pragma unroll
    for (int it = 0; it < 4; it++) {
        aG[it] = A + (size_t)(m0 + it * 32 + aRow) * K + aC16 * 4;
        aS[it] = (uint32_t)((it * 32 + aRow) * 144 + aC16 * 16);
    }
    // B: 4 chunks: k-row = it*8 + (tid>>5), n-chunk = (tid&31)
    const int bRow = tid >> 5;
    const int bC16 = tid & 31;
    const float* bG[4];
    uint32_t bS[4];
#pragma unroll
    for (int it = 0; it < 4; it++) {
        bG[it] = W + (size_t)(it * 8 + bRow) * N_ + n0 + bC16 * 4;
        bS[it] = (uint32_t)((it * 8 + bRow) * 544 + bC16 * 16);
    }

    auto issue = [&](int k0, int buf) {
        uint32_t ab = aBase + buf * (kABufF * 4);
        uint32_t bb = bBase + buf * (kBBufF * 4);
#pragma unroll
        for (int it = 0; it < 4; it++)
            CP_ASYNC16(ab + aS[it], aG[it] + k0);
        size_t wof = (size_t)k0 * N_;
#pragma unroll
        for (int it = 0; it < 4; it++)
            CP_ASYNC16(bb + bS[it], bG[it] + wof);
        CP_COMMIT();
    };

    float acc[4][4][4];
#pragma unroll
    for (int i = 0; i < 4; i++)
#pragma unroll
        for (int j = 0; j < 4; j++)
#pragma unroll
            for (int c = 0; c < 4; c++) acc[i][j][c] = 0.f;

    issue(0, 0);
    issue(32, 1);

    const int arow0 = wm * 64 + gid;
    const int nb0   = wn * 32 + gid;

    for (int s = 0; s < K / 32; s++) {
        if (s < K / 32 - 1) CP_WAIT1(); else CP_WAIT0();
        __syncthreads();

        const float* ab = As + (s & 1) * kABufF;
        const float* bb = Bs + (s & 1) * kBBufF;
#pragma unroll
        for (int kc = 0; kc < 4; kc++) {
            const int kcol = kc * 8 + tig;
            uint32_t a[4][4], b[4][2];
#pragma unroll
            for (int mt = 0; mt < 4; mt++) {
                const float* p = ab + (arow0 + mt * 16) * kAStrideF + kcol;
                a[mt][0] = __float_as_uint(p[0]);
                a[mt][1] = __float_as_uint(p[8 * kAStrideF]);
                a[mt][2] = __float_as_uint(p[4]);
                a[mt][3] = __float_as_uint(p[8 * kAStrideF + 4]);
            }
#pragma unroll
            for (int nt = 0; nt < 4; nt++) {
                const float* q = bb + kcol * kBStrideF + nb0 + nt * 8;
                b[nt][0] = __float_as_uint(q[0]);
                b[nt][1] = __float_as_uint(q[4 * kBStrideF]);
            }
#pragma unroll
            for (int mt = 0; mt < 4; mt++)
#pragma unroll
                for (int nt = 0; nt < 4; nt++)
                    mma_tf32(acc[mt][nt], a[mt], b[nt]);
        }
        __syncthreads();
        if (s + 2 < K / 32) issue((s + 2) * 32, s & 1);
    }

    // ---- epilogue ----
#pragma unroll
    for (int mt = 0; mt < 4; mt++)
#pragma unroll
        for (int nt = 0; nt < 4; nt++)
#pragma unroll
            for (int c = 0; c < 4; c++) {
                int m = m0 + wm * 64 + mt * 16 + gid + 8 * (c >> 1);
                int n = n0 + wn * 32 + nt * 8 + tig * 2 + (c & 1);
                epi(m, n, acc[mt][nt][c]);
            }
}

struct QkvEpilogue {
    const float* bias;
    float* kout;
    float* vout;
    __device__ __forceinline__ void operator()(int m, int n, float v) const {
        v += bias[n];
        int bidx = m >> 11;
        int t    = m & 2047;
        int s = n >> 10;
        int cc = n & 1023;
        int h = cc >> 6, d = cc & 63;
        int idx = ((bidx * kH + h) * kT + t) * kHD + d;
        if (s == 0)      g_q[idx]  = v;
        else if (s == 1) kout[idx] = v;
        else             vout[idx] = v;
    }
};

__global__ void __launch_bounds__(256, 2) qkv_gemm_kernel(
    const float* __restrict__ bias,
    float* __restrict__ kout, float* __restrict__ vout)
{
    QkvEpilogue epi{bias, kout, vout};
    gemm_tf32_core<3 * kC>(g_xc, g_wc, epi);
}

struct ProjEpilogue {
    const float* bias;
    float* out;
    __device__ __forceinline__ void operator()(int m, int n, float v) const {
        out[(size_t)m * kC + n] = v + bias[n];
    }
};

__global__ void __launch_bounds__(256, 2) proj_gemm_kernel(
    const float* __restrict__ bias, float* __restrict__ out)
{
    ProjEpilogue epi{bias, out};
    gemm_tf32_core<kC>(g_yatt, g_wp, epi);
}

// ---------------------------------------------------------------------------
// TF32 MMA flash attention (R3 core). BR=BC=64, 128 threads = 4 warps.
// Output to g_yatt is tf32-rounded (proj consumes it without converting).
// ---------------------------------------------------------------------------
constexpr int kFlashSmemBytes = 3 * 64 * 68 * 4;

__global__ void __launch_bounds__(128) flash_kernel(
    const float* __restrict__ Kg, const float* __restrict__ Vg)
{
    extern __shared__ float sm[];
    float* Ks = sm;               // [64][68]
    float* Vt = sm + 64 * 68;     // [64][68]  (Vt[d][c])
    float* Ss = sm + 2 * 64 * 68; // [64][68]

    const int tid  = threadIdx.x;
    const int lane = tid & 31;
    const int wid  = tid >> 5;
    const int gid  = lane >> 2;
    const int tig  = lane & 3;
    const int qi = blockIdx.x, h = blockIdx.y, b = blockIdx.z;
    const int qbase = qi * 64;
    const int r0 = wid * 16;

    const size_t head_off = (size_t)(b * kH + h) * kT * kHD;
    const float* Qp = g_q + head_off;
    const float* Kp = Kg + head_off;
    const float* Vp = Vg + head_off;

#pragma unroll
    for (int it = 0; it < 8; it++) {
        int f = it * 128 + tid;
        int r = f >> 4, dq = (f & 15) * 4;
        float4 q4 = *reinterpret_cast<const float4*>(Qp + (size_t)(qbase + r) * kHD + dq);
        float* d = Ss + r * 68 + dq;
        d[0] = q4.x; d[1] = q4.y; d[2] = q4.z; d[3] = q4.w;
    }
    __syncthreads();

    uint32_t qf[8][4];
#pragma unroll
    for (int kc = 0; kc < 8; kc++) {
        const float* base = Ss + (r0 + gid) * 68 + kc * 8 + tig;
        qf[kc][0] = __float_as_uint(to_tf32(0.125f * base[0]));
        qf[kc][1] = __float_as_uint(to_tf32(0.125f * base[8 * 68]));
        qf[kc][2] = __float_as_uint(to_tf32(0.125f * base[4]));
        qf[kc][3] = __float_as_uint(to_tf32(0.125f * base[8 * 68 + 4]));
    }

    float mA = -INFINITY, mB = -INFINITY, lA = 0.f, lB = 0.f;
    float oacc[8][4];
#pragma unroll
    for (int nt = 0; nt < 8; nt++)
#pragma unroll
        for (int c = 0; c < 4; c++) oacc[nt][c] = 0.f;

    const int ntiles = qi + 1;
    const int vdpb = tid & 15, vcb4 = tid >> 4;

    for (int jt = 0; jt < ntiles; jt++) {
        __syncthreads();
#pragma unroll
        for (int it = 0; it < 8; it++) {
            int f = it * 128 + tid;
            int r = f >> 4, dq = (f & 15) * 4;
            float4 k4 = *reinterpret_cast<const float4*>(Kp + (size_t)(jt * 64 + r) * kHD + dq);
            float* d = Ks + r * 68 + dq;
            d[0] = to_tf32(k4.x); d[1] = to_tf32(k4.y);
            d[2] = to_tf32(k4.z); d[3] = to_tf32(k4.w);
        }
#pragma unroll
        for (int it = 0; it < 2; it++) {
            int cb = vcb4 + 8 * it;
            const float* vsrc = Vp + (size_t)(jt * 64 + cb * 4) * kHD + vdpb * 4;
            float4 a0 = *reinterpret_cast<const float4*>(vsrc);
            float4 a1 = *reinterpret_cast<const float4*>(vsrc + kHD);
            float4 a2 = *reinterpret_cast<const float4*>(vsrc + 2 * kHD);
            float4 a3 = *reinterpret_cast<const float4*>(vsrc + 3 * kHD);
            float4 t0 = {to_tf32(a0.x), to_tf32(a1.x), to_tf32(a2.x), to_tf32(a3.x)};
            float4 t1 = {to_tf32(a0.y), to_tf32(a1.y), to_tf32(a2.y), to_tf32(a3.y)};
            float4 t2 = {to_tf32(a0.z), to_tf32(a1.z), to_tf32(a2.z), to_tf32(a3.z)};
            float4 t3 = {to_tf32(a0.w), to_tf32(a1.w), to_tf32(a2.w), to_tf32(a3.w)};
            *reinterpret_cast<float4*>(Vt + (vdpb * 4 + 0) * 68 + cb * 4) = t0;
            *reinterpret_cast<float4*>(Vt + (vdpb * 4 + 1) * 68 + cb * 4) = t1;
            *reinterpret_cast<float4*>(Vt + (vdpb * 4 + 2) * 68 + cb * 4) = t2;
            *reinterpret_cast<float4*>(Vt + (vdpb * 4 + 3) * 68 + cb * 4) = t3;
        }
        __syncthreads();

        float sa[8][4];
#pragma unroll
        for (int nt = 0; nt < 8; nt++)
#pragma unroll
            for (int c = 0; c < 4; c++) sa[nt][c] = 0.f;
#pragma unroll
        for (int kc = 0; kc < 8; kc++) {
#pragma unroll
            for (int nt = 0; nt < 8; nt++) {
                const float* bp = Ks + (nt * 8 + gid) * 68 + kc * 8 + tig;
                uint32_t bb[2];
                bb[0] = __float_as_uint(bp[0]);
                bb[1] = __float_as_uint(bp[4]);
                mma_tf32(sa[nt], qf[kc], bb);
            }
        }

        if (jt == qi) {
            int rowA = r0 + gid, rowB = rowA + 8;
#pragma unroll
            for (int nt = 0; nt < 8; nt++) {
                int c0 = nt * 8 + tig * 2, c1 = c0 + 1;
                if (c0 > rowA) sa[nt][0] = -INFINITY;
                if (c1 > rowA) sa[nt][1] = -INFINITY;
                if (c0 > rowB) sa[nt][2] = -INFINITY;
                if (c1 > rowB) sa[nt][3] = -INFINITY;
            }
        }

        float mxA = -INFINITY, mxB = -INFINITY;
#pragma unroll
        for (int nt = 0; nt < 8; nt++) {
            mxA = fmaxf(mxA, fmaxf(sa[nt][0], sa[nt][1]));
            mxB = fmaxf(mxB, fmaxf(sa[nt][2], sa[nt][3]));
        }
        mxA = fmaxf(mxA, __shfl_xor_sync(0xffffffff, mxA, 1));
        mxA = fmaxf(mxA, __shfl_xor_sync(0xffffffff, mxA, 2));
        mxB = fmaxf(mxB, __shfl_xor_sync(0xffffffff, mxB, 1));
        mxB = fmaxf(mxB, __shfl_xor_sync(0xffffffff, mxB, 2));

        float mnA = fmaxf(mA, mxA), mnB = fmaxf(mB, mxB);
        float alphaA = __expf(mA - mnA), alphaB = __expf(mB - mnB);

        float sumA = 0.f, sumB = 0.f;
        float* prowA = Ss + (r0 + gid) * 68 + tig * 2;
        float* prowB = prowA + 8 * 68;
#pragma unroll
        for (int nt = 0; nt < 8; nt++) {
            float p0 = __expf(sa[nt][0] - mnA);
            float p1 = __expf(sa[nt][1] - mnA);
            float p2 = __expf(sa[nt][2] - mnB);
            float p3 = __expf(sa[nt][3] - mnB);
            float q0 = to_tf32(p0), q1 = to_tf32(p1);
            float q2 = to_tf32(p2), q3 = to_tf32(p3);
            sumA += q0 + q1;
            sumB += q2 + q3;
            prowA[nt * 8 + 0] = q0; prowA[nt * 8 + 1] = q1;
            prowB[nt * 8 + 0] = q2; prowB[nt * 8 + 1] = q3;
        }
        sumA += __shfl_xor_sync(0xffffffff, sumA, 1);
        sumA += __shfl_xor_sync(0xffffffff, sumA, 2);
        sumB += __shfl_xor_sync(0xffffffff, sumB, 1);
        sumB += __shfl_xor_sync(0xffffffff, sumB, 2);

        lA = lA * alphaA + sumA;  mA = mnA;
        lB = lB * alphaB + sumB;  mB = mnB;

#pragma unroll
        for (int nt = 0; nt < 8; nt++) {
            oacc[nt][0] *= alphaA; oacc[nt][1] *= alphaA;
            oacc[nt][2] *= alphaB; oacc[nt][3] *= alphaB;
        }
        __syncwarp();

#pragma unroll
        for (int kc = 0; kc < 8; kc++) {
            const float* ap = Ss + (r0 + gid) * 68 + kc * 8 + tig;
            uint32_t pa[4];
            pa[0] = __float_as_uint(ap[0]);
            pa[1] = __float_as_uint(ap[8 * 68]);
            pa[2] = __float_as_uint(ap[4]);
            pa[3] = __float_as_uint(ap[8 * 68 + 4]);
#pragma unroll
            for (int nt = 0; nt < 8; nt++) {
                const float* bp = Vt + (nt * 8 + gid) * 68 + kc * 8 + tig;
                uint32_t bb[2];
                bb[0] = __float_as_uint(bp[0]);
                bb[1] = __float_as_uint(bp[4]);
                mma_tf32(oacc[nt], pa, bb);
            }
        }
        __syncwarp();
    }

    // Output is tf32-rounded so proj can consume it without converting.
    float ilA = 1.f / lA, ilB = 1.f / lB;
    float* ypA = g_yatt + ((size_t)(b * kT + qbase + r0 + gid)) * kC + h * kHD;
    float* ypB = ypA + (size_t)8 * kC;
#pragma unroll
    for (int nt = 0; nt < 8; nt++) {
        float2 vA = {to_tf32(oacc[nt][0] * ilA), to_tf32(oacc[nt][1] * ilA)};
        float2 vB = {to_tf32(oacc[nt][2] * ilB), to_tf32(oacc[nt][3] * ilB)};
        *reinterpret_cast<float2*>(ypA + nt * 8 + tig * 2) = vA;
        *reinterpret_cast<float2*>(ypB + nt * 8 + tig * 2) = vB;
    }
}

// ---------------------------------------------------------------------------
// Launch: cvt -> qkv -> flash -> proj, sequential default stream (capturable).
// Output layout: [ y (B*T*C) | k (B*H*T*hd) | v (B*H*T*hd) ]
// ---------------------------------------------------------------------------
extern "C" void kernel_launch(void* const* d_in, const int* in_sizes, int n_in,
                              void* d_out, int out_size)
{
    const float* x      = (const float*)d_in[0];
    const float* W_attn = (const float*)d_in[1];
    const float* b_attn = (const float*)d_in[2];
    const float* W_proj = (const float*)d_in[3];
    const float* b_proj = (const float*)d_in[4];

    float* y = (float*)d_out;
    const int seg = out_size / 3;       // 4,194,304 each
    float* kout = y + seg;
    float* vout = y + 2 * seg;

    cudaFuncSetAttribute(qkv_gemm_kernel,
                         cudaFuncAttributeMaxDynamicSharedMemorySize, kGemmSmemBytes);
    cudaFuncSetAttribute(proj_gemm_kernel,
                         cudaFuncAttributeMaxDynamicSharedMemorySize, kGemmSmemBytes);
    cudaFuncSetAttribute(flash_kernel,
                         cudaFuncAttributeMaxDynamicSharedMemorySize, kFlashSmemBytes);

    cvt_tf32_kernel<<<kCvtTotal4 / 256, 256>>>(x, W_attn, W_proj);
    // QKV: M=4096 -> 32 m-tiles, N=3072 -> 24 n-tiles
    qkv_gemm_kernel<<<dim3(24, 32), 256, kGemmSmemBytes>>>(b_attn, kout, vout);
    // Attention: (T/64, H, B)
    flash_kernel<<<dim3(32, 16, 2), 128, kFlashSmemBytes>>>(kout, vout);
    // Proj: N=1024 -> 8 n-tiles
    proj_gemm_kernel<<<dim3(8, 32), 256, kGemmSmemBytes>>>(b_proj, y);
}